// round 5
// baseline (speedup 1.0000x reference)
#include <cuda_runtime.h>
#include <cuda_bf16.h>
#include <math.h>

#define NUM_N 100000
#define NUM_E 1600000
#define NUM_G 128
#define D_IN 128

#define GRID  148
#define TPB   1024
#define GT    (GRID * TPB)        // 151552 threads
#define NWARP (GT / 32)           // 4736 warps
#define CHUNK 676                 // 148*676 = 100048 >= NUM_N

// -------- device scratch (statics start zeroed) ----------------------------
__device__ int   g_bar[8];           // grid-barrier slots (cyclic reset, 6 used)
__device__ int   g_batch[NUM_N];
__device__ int   g_deg[NUM_N];       // re-zeroed for next replay in final phase
__device__ float g_dinv[NUM_N];
__device__ int   g_woff[NUM_N];
__device__ int   g_csrc[NUM_E];
__device__ int   g_bsum[GRID];
__device__ int   g_pcnt[NUM_G];      // re-zeroed in prop1 phase
__device__ int   g_pcnt2[NUM_G];     // pristine copy for pool/mlp
__device__ int   g_boff[NUM_G];      // working copy (consumed by scatter)
__device__ int   g_boff2[NUM_G];     // pristine copy (pool start offsets)
__device__ int   g_bnode[NUM_N];
__device__ float g_h1[NUM_N * 16];   // (x @ W1) * dinv  (dinv fused in epilogue)
__device__ float g_q [NUM_N * 16];
__device__ float g_r [NUM_N * 16];

// -------- software grid barrier: RED arrive + volatile-load poll -----------
__device__ __forceinline__ void grid_sync(int j) {
    __syncthreads();
    __threadfence();                       // release + L1 flush
    if (threadIdx.x == 0) {
        if (atomicAdd(&g_bar[j], 1) == GRID - 1) {
            atomicExch(&g_bar[(j + 4) % 6], 0);    // reset a stale slot
        } else {
            while (*((volatile int*)&g_bar[j]) < GRID) { }
        }
    }
    __syncthreads();
    __threadfence();                       // acquire + L1 flush (CCTL.IVALL)
}

__global__ __launch_bounds__(TPB, 1) void mega_kernel(
    const float* __restrict__ x, const void* ei, const void* bat,
    const float* __restrict__ W1, const float* __restrict__ b1,
    const float* __restrict__ W2, const float* __restrict__ b2,
    const float* __restrict__ LW1, const float* __restrict__ Lb1,
    const float* __restrict__ LW2, const float* __restrict__ Lb2,
    float* __restrict__ out)
{
    __shared__ float4 w1s[512];      // W1 (8KB)
    __shared__ float4 w2s[512];      // W2 (8KB)
    __shared__ float4 red[1024];     // pool partials (16KB)
    __shared__ int    wsum[32];
    __shared__ int    s_i32, s_base;
    __shared__ float  ps[128], z1[128], z2[2];

    const int tid  = threadIdx.x, bid = blockIdx.x;
    const int lane = tid & 31,    wid = tid >> 5;
    const int gth  = bid * TPB + tid;
    const int gw   = gth >> 5;

    // ---- detect int64 vs int32 index layout (per block, 64 samples) ----
    if (tid == 0) s_i32 = 0;
    __syncthreads();
    if (tid < 64) {
        long long v = ((const long long*)ei)[(size_t)tid * (NUM_E / 64)];
        if (v < 0 || v >= (long long)NUM_N) s_i32 = 1;
    }
    __syncthreads();
    const bool f64 = (s_i32 == 0);

    // ================= P0: degree + batch histograms =======================
    for (int i = gth; i < NUM_E; i += GT) {
        int d = f64 ? (int)((const long long*)ei)[NUM_E + i]
                    : ((const int*)ei)[NUM_E + i];
        atomicAdd(&g_deg[d], 1);
    }
    for (int i = gth; i < NUM_N; i += GT) {
        int b = f64 ? (int)((const long long*)bat)[i] : ((const int*)bat)[i];
        g_batch[i] = b;
        atomicAdd(&g_pcnt[b], 1);
    }
    grid_sync(0);

    // ================= P1: block-local scan of deg (+dinv, batch scan) =====
    const int node = bid * CHUNK + tid;
    const bool nvalid = (tid < CHUNK) && (node < NUM_N);
    int deg = nvalid ? g_deg[node] : 0;
    int v = deg;
    #pragma unroll
    for (int o = 1; o < 32; o <<= 1) {
        int n = __shfl_up_sync(~0u, v, o);
        if (lane >= o) v += n;
    }
    if (lane == 31) wsum[wid] = v;
    __syncthreads();
    if (wid == 0) {
        int wv = wsum[lane];
        #pragma unroll
        for (int o = 1; o < 32; o <<= 1) {
            int n = __shfl_up_sync(~0u, wv, o);
            if (lane >= o) wv += n;
        }
        wsum[lane] = wv;
    }
    __syncthreads();
    const int ex_local = (wid ? wsum[wid - 1] : 0) + v - deg;
    if (tid == 0) g_bsum[bid] = wsum[31];
    if (nvalid) g_dinv[node] = rsqrtf((float)deg + 1.f);
    if (bid == 0 && wid == 31) {   // batch scan + pristine copies
        int p0 = g_pcnt[lane*4+0], p1 = g_pcnt[lane*4+1];
        int p2 = g_pcnt[lane*4+2], p3 = g_pcnt[lane*4+3];
        int t1 = p0 + p1, t2 = t1 + p2, t3 = t2 + p3;
        int vv = t3;
        #pragma unroll
        for (int o = 1; o < 32; o <<= 1) {
            int n = __shfl_up_sync(~0u, vv, o);
            if (lane >= o) vv += n;
        }
        int exb = vv - t3;
        g_boff [lane*4+0] = exb;      g_boff2[lane*4+0] = exb;
        g_boff [lane*4+1] = exb+p0;   g_boff2[lane*4+1] = exb+p0;
        g_boff [lane*4+2] = exb+t1;   g_boff2[lane*4+2] = exb+t1;
        g_boff [lane*4+3] = exb+t2;   g_boff2[lane*4+3] = exb+t2;
        g_pcnt2[lane*4+0] = p0; g_pcnt2[lane*4+1] = p1;
        g_pcnt2[lane*4+2] = p2; g_pcnt2[lane*4+3] = p3;
    }
    grid_sync(1);

    // ================= P2: each block derives its global base, writes woff ==
    if (wid == 0) {
        int s = 0;
        for (int i = lane; i < bid; i += 32) s += g_bsum[i];
        #pragma unroll
        for (int o = 16; o; o >>= 1) s += __shfl_xor_sync(~0u, s, o);
        if (lane == 0) s_base = s;
    }
    __syncthreads();
    if (nvalid) g_woff[node] = s_base + ex_local;
    grid_sync(2);

    // ================= P3: scatter edges + bnode, then gemm1 (dinv fused) ==
    for (int i = gth; i < NUM_E; i += GT) {
        int s, d;
        if (f64) {
            s = (int)((const long long*)ei)[i];
            d = (int)((const long long*)ei)[NUM_E + i];
        } else {
            s = ((const int*)ei)[i];
            d = ((const int*)ei)[NUM_E + i];
        }
        g_csrc[atomicAdd(&g_woff[d], 1)] = s;
    }
    for (int i = gth; i < NUM_N; i += GT) {
        int b = g_batch[i];
        g_bnode[atomicAdd(&g_boff[b], 1)] = i;
    }
    for (int i = tid; i < 512; i += TPB) w1s[i] = ((const float4*)W1)[i];
    __syncthreads();
    for (int w = gw; w < NUM_N; w += NWARP) {
        float4 xv = ((const float4*)x)[(size_t)w * 32 + lane];
        float a[16];
        #pragma unroll
        for (int j = 0; j < 16; j++) a[j] = 0.f;
        {
            float xs[4] = {xv.x, xv.y, xv.z, xv.w};
            int kb4 = lane * 16;
            #pragma unroll
            for (int kk = 0; kk < 4; kk++) {
                float c = xs[kk];
                #pragma unroll
                for (int q = 0; q < 4; q++) {
                    float4 wv = w1s[kb4 + kk * 4 + q];
                    a[q*4+0] = fmaf(c, wv.x, a[q*4+0]);
                    a[q*4+1] = fmaf(c, wv.y, a[q*4+1]);
                    a[q*4+2] = fmaf(c, wv.z, a[q*4+2]);
                    a[q*4+3] = fmaf(c, wv.w, a[q*4+3]);
                }
            }
        }
        // halving butterfly: 16 outputs over 32 lanes
        {
            float t[16];
            #pragma unroll
            for (int i = 0; i < 16; i++) t[i] = __shfl_xor_sync(~0u, a[i], 16);
            if ((lane & 16) == 0) {
                #pragma unroll
                for (int i = 0; i < 8; i++) a[i] += t[i]; }
            else {
                #pragma unroll
                for (int i = 0; i < 8; i++) a[i] = a[i+8] + t[i+8]; }
        }
        {
            float t[8];
            #pragma unroll
            for (int i = 0; i < 8; i++) t[i] = __shfl_xor_sync(~0u, a[i], 8);
            if ((lane & 8) == 0) {
                #pragma unroll
                for (int i = 0; i < 4; i++) a[i] += t[i]; }
            else {
                #pragma unroll
                for (int i = 0; i < 4; i++) a[i] = a[i+4] + t[i+4]; }
        }
        {
            float t[4];
            #pragma unroll
            for (int i = 0; i < 4; i++) t[i] = __shfl_xor_sync(~0u, a[i], 4);
            if ((lane & 4) == 0) { a[0] += t[0]; a[1] += t[1]; }
            else                 { a[0] = a[2] + t[2]; a[1] = a[3] + t[3]; }
        }
        {
            float t0 = __shfl_xor_sync(~0u, a[0], 2);
            float t1 = __shfl_xor_sync(~0u, a[1], 2);
            if ((lane & 2) == 0) a[0] += t0; else a[0] = a[1] + t1;
        }
        a[0] += __shfl_xor_sync(~0u, a[0], 1);
        float dvd = g_dinv[w];
        if ((lane & 1) == 0) g_h1[(size_t)w * 16 + (lane >> 1)] = a[0] * dvd;
    }
    grid_sync(3);

    // ================= P4: prop1 (+zero pcnt for next replay) ==============
    if (bid == GRID - 1 && tid < NUM_G) g_pcnt[tid] = 0;
    for (int w = gw; w < NUM_N; w += NWARP) {
        int sub = lane & 3, grp = lane >> 2;
        int dg = g_deg[w];
        int start = g_woff[w] - dg;
        float ax = 0.f, ay = 0.f, az = 0.f, aw = 0.f;
        for (int e = grp; e < dg; e += 8) {
            int s = g_csrc[start + e];
            float4 vv = ((const float4*)g_h1)[s * 4 + sub];
            ax += vv.x; ay += vv.y; az += vv.z; aw += vv.w;
        }
        #pragma unroll
        for (int o = 4; o < 32; o <<= 1) {
            ax += __shfl_xor_sync(~0u, ax, o);
            ay += __shfl_xor_sync(~0u, ay, o);
            az += __shfl_xor_sync(~0u, az, o);
            aw += __shfl_xor_sync(~0u, aw, o);
        }
        if (lane < 4) {
            float dvd = g_dinv[w];
            float4 hs = ((const float4*)g_h1)[w * 4 + sub];
            float4 bv = ((const float4*)b1)[sub];
            float4 o;
            o.x = fmaxf(fmaf(dvd, ax + hs.x, bv.x), 0.f) * dvd;
            o.y = fmaxf(fmaf(dvd, ay + hs.y, bv.y), 0.f) * dvd;
            o.z = fmaxf(fmaf(dvd, az + hs.z, bv.z), 0.f) * dvd;
            o.w = fmaxf(fmaf(dvd, aw + hs.w, bv.w), 0.f) * dvd;
            ((float4*)g_q)[w * 4 + sub] = o;
        }
    }
    grid_sync(4);

    // ================= P5: prop2 ===========================================
    for (int w = gw; w < NUM_N; w += NWARP) {
        int sub = lane & 3, grp = lane >> 2;
        int dg = g_deg[w];
        int start = g_woff[w] - dg;
        float ax = 0.f, ay = 0.f, az = 0.f, aw = 0.f;
        for (int e = grp; e < dg; e += 8) {
            int s = g_csrc[start + e];
            float4 vv = ((const float4*)g_q)[s * 4 + sub];
            ax += vv.x; ay += vv.y; az += vv.z; aw += vv.w;
        }
        #pragma unroll
        for (int o = 4; o < 32; o <<= 1) {
            ax += __shfl_xor_sync(~0u, ax, o);
            ay += __shfl_xor_sync(~0u, ay, o);
            az += __shfl_xor_sync(~0u, az, o);
            aw += __shfl_xor_sync(~0u, aw, o);
        }
        if (lane < 4) {
            float dvd = g_dinv[w];
            float4 qs = ((const float4*)g_q)[w * 4 + sub];
            float4 o;
            o.x = dvd * (ax + qs.x); o.y = dvd * (ay + qs.y);
            o.z = dvd * (az + qs.z); o.w = dvd * (aw + qs.w);
            ((float4*)g_r)[w * 4 + sub] = o;
        }
    }
    grid_sync(5);

    // ================= P6: pool + gemm2 + mlp (blocks 0..127) ==============
    if (bid < NUM_G) {
        for (int i = tid; i < 512; i += TPB) w2s[i] = ((const float4*)W2)[i];
        __syncthreads();
        const int g = bid;
        const int cnt = g_pcnt2[g];
        const int start = g_boff2[g];
        float4 bv = ((const float4*)b2)[lane];
        float4 sum = make_float4(0.f, 0.f, 0.f, 0.f);
        for (int i = wid; i < cnt; i += 32) {
            int n = g_bnode[start + i];
            float rv = (lane < 16) ? g_r[n * 16 + lane] : 0.f;
            float4 acc = bv;
            #pragma unroll
            for (int k = 0; k < 16; k++) {
                float s = __shfl_sync(~0u, rv, k);
                float4 wv = w2s[k * 32 + lane];
                acc.x = fmaf(s, wv.x, acc.x); acc.y = fmaf(s, wv.y, acc.y);
                acc.z = fmaf(s, wv.z, acc.z); acc.w = fmaf(s, wv.w, acc.w);
            }
            sum.x += fmaxf(acc.x, 0.f); sum.y += fmaxf(acc.y, 0.f);
            sum.z += fmaxf(acc.z, 0.f); sum.w += fmaxf(acc.w, 0.f);
        }
        red[wid * 32 + lane] = sum;
        __syncthreads();
        if (tid < 32) {
            float4 tot = red[tid];
            #pragma unroll
            for (int w2 = 1; w2 < 32; w2++) {
                float4 vv = red[w2 * 32 + tid];
                tot.x += vv.x; tot.y += vv.y; tot.z += vv.z; tot.w += vv.w;
            }
            float inv = 1.f / fmaxf((float)cnt, 1.f);
            ps[tid * 4 + 0] = tot.x * inv; ps[tid * 4 + 1] = tot.y * inv;
            ps[tid * 4 + 2] = tot.z * inv; ps[tid * 4 + 3] = tot.w * inv;
        }
        __syncthreads();
        if (tid < 128) {
            float acc = Lb1[tid];
            #pragma unroll 8
            for (int k = 0; k < 128; k++) acc = fmaf(ps[k], LW1[k * 128 + tid], acc);
            z1[tid] = fmaxf(acc, 0.f);
        }
        __syncthreads();
        if (tid < 2) {
            float a = Lb2[tid];
            for (int k = 0; k < 128; k++) a = fmaf(z1[k], LW2[k * 2 + tid], a);
            z2[tid] = a;
        }
        __syncthreads();
        if (tid == 0) {
            float m = fmaxf(z2[0], z2[1]);
            float lse = m + logf(expf(z2[0] - m) + expf(z2[1] - m));
            out[g * 2 + 0] = z2[0] - lse;
            out[g * 2 + 1] = z2[1] - lse;
        }
    } else {
        // idle blocks: zero g_deg for the next replay
        for (int i = (bid - NUM_G) * TPB + tid; i < NUM_N; i += (GRID - NUM_G) * TPB)
            g_deg[i] = 0;
    }
}

// -------- launch --------
extern "C" void kernel_launch(void* const* d_in, const int* in_sizes, int n_in,
                              void* d_out, int out_size) {
    const float* x   = (const float*)d_in[0];
    const void*  ei  = d_in[1];
    const void*  bat = d_in[2];
    const float* W1  = (const float*)d_in[3];
    const float* b1  = (const float*)d_in[4];
    const float* W2  = (const float*)d_in[5];
    const float* b2  = (const float*)d_in[6];
    const float* LW1 = (const float*)d_in[7];
    const float* Lb1 = (const float*)d_in[8];
    const float* LW2 = (const float*)d_in[9];
    const float* Lb2 = (const float*)d_in[10];
    float* out = (float*)d_out;

    mega_kernel<<<GRID, TPB>>>(x, ei, bat, W1, b1, W2, b2,
                               LW1, Lb1, LW2, Lb2, out);
}

// round 6
// speedup vs baseline: 1.1154x; 1.1154x over previous
#include <cuda_runtime.h>
#include <cuda_bf16.h>
#include <math.h>

#define NUM_N 100000
#define NUM_E 1600000
#define NUM_G 128
#define D_IN 128

#define GRID  148
#define TPB   1024
#define GT    (GRID * TPB)        // 151552 threads
#define NWARP (GT / 32)           // 4736 warps
#define CHUNK 676                 // 148*676 = 100048 >= NUM_N
#define NE2   (NUM_E / 2)         // 800000 edge pairs

// -------- device scratch (statics start zeroed) ----------------------------
__device__ int   g_bar[8];           // grid-barrier slots (cyclic reset, 6 used)
__device__ int   g_batch[NUM_N];
__device__ int   g_deg[NUM_N];       // re-zeroed for next replay in final phase
__device__ float g_dinv[NUM_N];
__device__ int   g_woff[NUM_N];
__device__ int   g_csrc[NUM_E];
__device__ int   g_bsum[GRID];
__device__ int   g_pcnt[NUM_G];      // re-zeroed in prop1 phase
__device__ int   g_pcnt2[NUM_G];     // pristine copy for pool/mlp
__device__ int   g_boff[NUM_G];      // working copy (consumed by scatter)
__device__ int   g_boff2[NUM_G];     // pristine copy (pool start offsets)
__device__ int   g_bnode[NUM_N];
__device__ float g_h1[NUM_N * 16];   // (x @ W1) * dinv
__device__ float g_q [NUM_N * 16];
__device__ float g_r [NUM_N * 16];

// -------- software grid barrier -------------------------------------------
__device__ __forceinline__ void grid_sync(int j) {
    __syncthreads();
    __threadfence();
    if (threadIdx.x == 0) {
        if (atomicAdd(&g_bar[j], 1) == GRID - 1) {
            atomicExch(&g_bar[(j + 4) % 6], 0);
        } else {
            while (*((volatile int*)&g_bar[j]) < GRID) { }
        }
    }
    __syncthreads();
    __threadfence();
}

__global__ __launch_bounds__(TPB, 1) void mega_kernel(
    const float* __restrict__ x, const void* ei, const void* bat,
    const float* __restrict__ W1, const float* __restrict__ b1,
    const float* __restrict__ W2, const float* __restrict__ b2,
    const float* __restrict__ LW1, const float* __restrict__ Lb1,
    const float* __restrict__ LW2, const float* __restrict__ Lb2,
    float* __restrict__ out)
{
    __shared__ float4 w1s[512];
    __shared__ float4 w2s[512];
    __shared__ float4 red[1024];
    __shared__ int    wsum[32];
    __shared__ int    s_i32, s_base;
    __shared__ float  ps[128], z1[128], z2[2];

    const int tid  = threadIdx.x, bid = blockIdx.x;
    const int lane = tid & 31,    wid = tid >> 5;
    const int gth  = bid * TPB + tid;
    const int gw   = gth >> 5;

    // ---- detect int64 vs int32 index layout ----
    if (tid == 0) s_i32 = 0;
    __syncthreads();
    if (tid < 64) {
        long long v = ((const long long*)ei)[(size_t)tid * (NUM_E / 64)];
        if (v < 0 || v >= (long long)NUM_N) s_i32 = 1;
    }
    __syncthreads();
    const bool f64 = (s_i32 == 0);

    // ================= P0: degree + batch histograms (2 edges/thread) ======
    for (int i = gth; i < NE2; i += GT) {
        int d0, d1;
        if (f64) { int4 v = ((const int4*)ei)[NE2 + i]; d0 = v.x; d1 = v.z; }
        else     { int2 v = ((const int2*)ei)[NE2 + i]; d0 = v.x; d1 = v.y; }
        atomicAdd(&g_deg[d0], 1);
        atomicAdd(&g_deg[d1], 1);
    }
    for (int i = gth; i < NUM_N; i += GT) {
        int b = f64 ? (int)((const long long*)bat)[i] : ((const int*)bat)[i];
        g_batch[i] = b;
        atomicAdd(&g_pcnt[b], 1);
    }
    grid_sync(0);

    // ================= P1: block-local scan of deg (+dinv, batch scan) =====
    const int node = bid * CHUNK + tid;
    const bool nvalid = (tid < CHUNK) && (node < NUM_N);
    int deg = nvalid ? g_deg[node] : 0;
    int v = deg;
    #pragma unroll
    for (int o = 1; o < 32; o <<= 1) {
        int n = __shfl_up_sync(~0u, v, o);
        if (lane >= o) v += n;
    }
    if (lane == 31) wsum[wid] = v;
    __syncthreads();
    if (wid == 0) {
        int wv = wsum[lane];
        #pragma unroll
        for (int o = 1; o < 32; o <<= 1) {
            int n = __shfl_up_sync(~0u, wv, o);
            if (lane >= o) wv += n;
        }
        wsum[lane] = wv;
    }
    __syncthreads();
    const int ex_local = (wid ? wsum[wid - 1] : 0) + v - deg;
    if (tid == 0) g_bsum[bid] = wsum[31];
    if (nvalid) g_dinv[node] = rsqrtf((float)deg + 1.f);
    if (bid == 0 && wid == 31) {
        int p0 = g_pcnt[lane*4+0], p1 = g_pcnt[lane*4+1];
        int p2 = g_pcnt[lane*4+2], p3 = g_pcnt[lane*4+3];
        int t1 = p0 + p1, t2 = t1 + p2, t3 = t2 + p3;
        int vv = t3;
        #pragma unroll
        for (int o = 1; o < 32; o <<= 1) {
            int n = __shfl_up_sync(~0u, vv, o);
            if (lane >= o) vv += n;
        }
        int exb = vv - t3;
        g_boff [lane*4+0] = exb;      g_boff2[lane*4+0] = exb;
        g_boff [lane*4+1] = exb+p0;   g_boff2[lane*4+1] = exb+p0;
        g_boff [lane*4+2] = exb+t1;   g_boff2[lane*4+2] = exb+t1;
        g_boff [lane*4+3] = exb+t2;   g_boff2[lane*4+3] = exb+t2;
        g_pcnt2[lane*4+0] = p0; g_pcnt2[lane*4+1] = p1;
        g_pcnt2[lane*4+2] = p2; g_pcnt2[lane*4+3] = p3;
    }
    grid_sync(1);

    // ================= P2: per-block global base, write woff ===============
    if (wid == 0) {
        int s = 0;
        for (int i = lane; i < bid; i += 32) s += g_bsum[i];
        #pragma unroll
        for (int o = 16; o; o >>= 1) s += __shfl_xor_sync(~0u, s, o);
        if (lane == 0) s_base = s;
    }
    __syncthreads();
    if (nvalid) g_woff[node] = s_base + ex_local;
    grid_sync(2);

    // ================= P3: scatter (2 edges/thread) + bnode + gemm1 ========
    for (int i = gth; i < NE2; i += GT) {
        int s0, s1, d0, d1;
        if (f64) {
            int4 sv = ((const int4*)ei)[i];       s0 = sv.x; s1 = sv.z;
            int4 dv = ((const int4*)ei)[NE2 + i]; d0 = dv.x; d1 = dv.z;
        } else {
            int2 sv = ((const int2*)ei)[i];       s0 = sv.x; s1 = sv.y;
            int2 dv = ((const int2*)ei)[NE2 + i]; d0 = dv.x; d1 = dv.y;
        }
        int p0 = atomicAdd(&g_woff[d0], 1);
        int p1 = atomicAdd(&g_woff[d1], 1);
        g_csrc[p0] = s0;
        g_csrc[p1] = s1;
    }
    for (int i = gth; i < NUM_N; i += GT) {
        int b = g_batch[i];
        g_bnode[atomicAdd(&g_boff[b], 1)] = i;
    }
    for (int i = tid; i < 512; i += TPB) w1s[i] = ((const float4*)W1)[i];
    __syncthreads();
    {   // gemm1 with double-buffered x row
        int w = gw;
        float4 xv = make_float4(0.f, 0.f, 0.f, 0.f);
        if (w < NUM_N) xv = ((const float4*)x)[(size_t)w * 32 + lane];
        for (; w < NUM_N; w += NWARP) {
            int wn = w + NWARP;
            float4 xvN = make_float4(0.f, 0.f, 0.f, 0.f);
            if (wn < NUM_N) xvN = ((const float4*)x)[(size_t)wn * 32 + lane];
            float dvd = g_dinv[w];
            float a[16];
            #pragma unroll
            for (int j = 0; j < 16; j++) a[j] = 0.f;
            {
                float xs[4] = {xv.x, xv.y, xv.z, xv.w};
                int kb4 = lane * 16;
                #pragma unroll
                for (int kk = 0; kk < 4; kk++) {
                    float c = xs[kk];
                    #pragma unroll
                    for (int q = 0; q < 4; q++) {
                        float4 wv = w1s[kb4 + kk * 4 + q];
                        a[q*4+0] = fmaf(c, wv.x, a[q*4+0]);
                        a[q*4+1] = fmaf(c, wv.y, a[q*4+1]);
                        a[q*4+2] = fmaf(c, wv.z, a[q*4+2]);
                        a[q*4+3] = fmaf(c, wv.w, a[q*4+3]);
                    }
                }
            }
            {   // halving butterfly
                float t[16];
                #pragma unroll
                for (int i = 0; i < 16; i++) t[i] = __shfl_xor_sync(~0u, a[i], 16);
                if ((lane & 16) == 0) {
                    #pragma unroll
                    for (int i = 0; i < 8; i++) a[i] += t[i]; }
                else {
                    #pragma unroll
                    for (int i = 0; i < 8; i++) a[i] = a[i+8] + t[i+8]; }
            }
            {
                float t[8];
                #pragma unroll
                for (int i = 0; i < 8; i++) t[i] = __shfl_xor_sync(~0u, a[i], 8);
                if ((lane & 8) == 0) {
                    #pragma unroll
                    for (int i = 0; i < 4; i++) a[i] += t[i]; }
                else {
                    #pragma unroll
                    for (int i = 0; i < 4; i++) a[i] = a[i+4] + t[i+4]; }
            }
            {
                float t[4];
                #pragma unroll
                for (int i = 0; i < 4; i++) t[i] = __shfl_xor_sync(~0u, a[i], 4);
                if ((lane & 4) == 0) { a[0] += t[0]; a[1] += t[1]; }
                else                 { a[0] = a[2] + t[2]; a[1] = a[3] + t[3]; }
            }
            {
                float t0 = __shfl_xor_sync(~0u, a[0], 2);
                float t1 = __shfl_xor_sync(~0u, a[1], 2);
                if ((lane & 2) == 0) a[0] += t0; else a[0] = a[1] + t1;
            }
            a[0] += __shfl_xor_sync(~0u, a[0], 1);
            if ((lane & 1) == 0) g_h1[(size_t)w * 16 + (lane >> 1)] = a[0] * dvd;
            xv = xvN;
        }
    }
    grid_sync(3);

    // ================= P4: prop1 (pipelined, 16 gathers in flight) =========
    if (bid == GRID - 1 && tid < NUM_G) g_pcnt[tid] = 0;
    {
        const int sub = lane & 3, grp = lane >> 2;
        int w = gw;
        int dgC = 0, stC = 0;
        if (w < NUM_N) { dgC = g_deg[w]; stC = g_woff[w] - dgC; }
        for (; w < NUM_N; w += NWARP) {
            int wn = w + NWARP;
            int dgN = 0, stN = 0;
            if (wn < NUM_N) { dgN = g_deg[wn]; stN = g_woff[wn] - dgN; }
            float ax0=0.f, ay0=0.f, az0=0.f, aw0=0.f;
            float ax1=0.f, ay1=0.f, az1=0.f, aw1=0.f;
            for (int e = grp; e < dgC; e += 16) {
                int e1 = e + 8;
                bool pr = (e1 < dgC);
                int s0 = g_csrc[stC + e];
                int s1 = pr ? g_csrc[stC + e1] : 0;
                float4 v0 = ((const float4*)g_h1)[s0 * 4 + sub];
                float4 v1 = ((const float4*)g_h1)[s1 * 4 + sub];
                ax0 += v0.x; ay0 += v0.y; az0 += v0.z; aw0 += v0.w;
                if (pr) { ax1 += v1.x; ay1 += v1.y; az1 += v1.z; aw1 += v1.w; }
            }
            float ax = ax0 + ax1, ay = ay0 + ay1, az = az0 + az1, aw = aw0 + aw1;
            #pragma unroll
            for (int o = 4; o < 32; o <<= 1) {
                ax += __shfl_xor_sync(~0u, ax, o);
                ay += __shfl_xor_sync(~0u, ay, o);
                az += __shfl_xor_sync(~0u, az, o);
                aw += __shfl_xor_sync(~0u, aw, o);
            }
            if (lane < 4) {
                float dvd = g_dinv[w];
                float4 hs = ((const float4*)g_h1)[w * 4 + sub];
                float4 bv = ((const float4*)b1)[sub];
                float4 o;
                o.x = fmaxf(fmaf(dvd, ax + hs.x, bv.x), 0.f) * dvd;
                o.y = fmaxf(fmaf(dvd, ay + hs.y, bv.y), 0.f) * dvd;
                o.z = fmaxf(fmaf(dvd, az + hs.z, bv.z), 0.f) * dvd;
                o.w = fmaxf(fmaf(dvd, aw + hs.w, bv.w), 0.f) * dvd;
                ((float4*)g_q)[w * 4 + sub] = o;
            }
            dgC = dgN; stC = stN;
        }
    }
    grid_sync(4);

    // ================= P5: prop2 (same pipeline) ===========================
    {
        const int sub = lane & 3, grp = lane >> 2;
        int w = gw;
        int dgC = 0, stC = 0;
        if (w < NUM_N) { dgC = g_deg[w]; stC = g_woff[w] - dgC; }
        for (; w < NUM_N; w += NWARP) {
            int wn = w + NWARP;
            int dgN = 0, stN = 0;
            if (wn < NUM_N) { dgN = g_deg[wn]; stN = g_woff[wn] - dgN; }
            float ax0=0.f, ay0=0.f, az0=0.f, aw0=0.f;
            float ax1=0.f, ay1=0.f, az1=0.f, aw1=0.f;
            for (int e = grp; e < dgC; e += 16) {
                int e1 = e + 8;
                bool pr = (e1 < dgC);
                int s0 = g_csrc[stC + e];
                int s1 = pr ? g_csrc[stC + e1] : 0;
                float4 v0 = ((const float4*)g_q)[s0 * 4 + sub];
                float4 v1 = ((const float4*)g_q)[s1 * 4 + sub];
                ax0 += v0.x; ay0 += v0.y; az0 += v0.z; aw0 += v0.w;
                if (pr) { ax1 += v1.x; ay1 += v1.y; az1 += v1.z; aw1 += v1.w; }
            }
            float ax = ax0 + ax1, ay = ay0 + ay1, az = az0 + az1, aw = aw0 + aw1;
            #pragma unroll
            for (int o = 4; o < 32; o <<= 1) {
                ax += __shfl_xor_sync(~0u, ax, o);
                ay += __shfl_xor_sync(~0u, ay, o);
                az += __shfl_xor_sync(~0u, az, o);
                aw += __shfl_xor_sync(~0u, aw, o);
            }
            if (lane < 4) {
                float dvd = g_dinv[w];
                float4 qs = ((const float4*)g_q)[w * 4 + sub];
                float4 o;
                o.x = dvd * (ax + qs.x); o.y = dvd * (ay + qs.y);
                o.z = dvd * (az + qs.z); o.w = dvd * (aw + qs.w);
                ((float4*)g_r)[w * 4 + sub] = o;
            }
            dgC = dgN; stC = stN;
        }
    }
    grid_sync(5);

    // ================= P6: pool + gemm2 + mlp (blocks 0..127) ==============
    if (bid < NUM_G) {
        for (int i = tid; i < 512; i += TPB) w2s[i] = ((const float4*)W2)[i];
        __syncthreads();
        const int g = bid;
        const int cnt = g_pcnt2[g];
        const int start = g_boff2[g];
        float4 bv = ((const float4*)b2)[lane];
        float4 sum = make_float4(0.f, 0.f, 0.f, 0.f);
        int i = wid;
        float rvN = 0.f;
        if (i < cnt) {
            int n = g_bnode[start + i];
            rvN = (lane < 16) ? g_r[n * 16 + lane] : 0.f;
        }
        for (; i < cnt; i += 32) {
            float rv = rvN;
            int in2 = i + 32;
            if (in2 < cnt) {
                int n2 = g_bnode[start + in2];
                rvN = (lane < 16) ? g_r[n2 * 16 + lane] : 0.f;
            }
            float4 acc = bv;
            #pragma unroll
            for (int k = 0; k < 16; k++) {
                float s = __shfl_sync(~0u, rv, k);
                float4 wv = w2s[k * 32 + lane];
                acc.x = fmaf(s, wv.x, acc.x); acc.y = fmaf(s, wv.y, acc.y);
                acc.z = fmaf(s, wv.z, acc.z); acc.w = fmaf(s, wv.w, acc.w);
            }
            sum.x += fmaxf(acc.x, 0.f); sum.y += fmaxf(acc.y, 0.f);
            sum.z += fmaxf(acc.z, 0.f); sum.w += fmaxf(acc.w, 0.f);
        }
        red[wid * 32 + lane] = sum;
        __syncthreads();
        if (tid < 32) {
            float4 tot = red[tid];
            #pragma unroll
            for (int w2 = 1; w2 < 32; w2++) {
                float4 vv = red[w2 * 32 + tid];
                tot.x += vv.x; tot.y += vv.y; tot.z += vv.z; tot.w += vv.w;
            }
            float inv = 1.f / fmaxf((float)cnt, 1.f);
            ps[tid * 4 + 0] = tot.x * inv; ps[tid * 4 + 1] = tot.y * inv;
            ps[tid * 4 + 2] = tot.z * inv; ps[tid * 4 + 3] = tot.w * inv;
        }
        __syncthreads();
        if (tid < 128) {
            float acc = Lb1[tid];
            #pragma unroll 8
            for (int k = 0; k < 128; k++) acc = fmaf(ps[k], LW1[k * 128 + tid], acc);
            z1[tid] = fmaxf(acc, 0.f);
        }
        __syncthreads();
        if (tid < 2) {
            float a = Lb2[tid];
            for (int k = 0; k < 128; k++) a = fmaf(z1[k], LW2[k * 2 + tid], a);
            z2[tid] = a;
        }
        __syncthreads();
        if (tid == 0) {
            float m = fmaxf(z2[0], z2[1]);
            float lse = m + logf(expf(z2[0] - m) + expf(z2[1] - m));
            out[g * 2 + 0] = z2[0] - lse;
            out[g * 2 + 1] = z2[1] - lse;
        }
    } else {
        for (int i = (bid - NUM_G) * TPB + tid; i < NUM_N; i += (GRID - NUM_G) * TPB)
            g_deg[i] = 0;
    }
}

// -------- launch --------
extern "C" void kernel_launch(void* const* d_in, const int* in_sizes, int n_in,
                              void* d_out, int out_size) {
    const float* x   = (const float*)d_in[0];
    const void*  ei  = d_in[1];
    const void*  bat = d_in[2];
    const float* W1  = (const float*)d_in[3];
    const float* b1  = (const float*)d_in[4];
    const float* W2  = (const float*)d_in[5];
    const float* b2  = (const float*)d_in[6];
    const float* LW1 = (const float*)d_in[7];
    const float* Lb1 = (const float*)d_in[8];
    const float* LW2 = (const float*)d_in[9];
    const float* Lb2 = (const float*)d_in[10];
    float* out = (float*)d_out;

    mega_kernel<<<GRID, TPB>>>(x, ei, bat, W1, b1, W2, b2,
                               LW1, Lb1, LW2, Lb2, out);
}

// round 7
// speedup vs baseline: 1.1312x; 1.0142x over previous
#include <cuda_runtime.h>
#include <cuda_fp16.h>
#include <math.h>

#define NUM_N 100000
#define NUM_E 1600000
#define NUM_G 128
#define D_IN 128

#define GRID  148
#define TPB   1024
#define GT    (GRID * TPB)        // 151552 threads
#define NWARP (GT / 32)           // 4736 warps
#define CHUNK 676                 // 148*676 >= NUM_N
#define NE2   (NUM_E / 2)         // 800000 edge pairs

// -------- device scratch (statics start zeroed) ----------------------------
__device__ int    g_bar[8];
__device__ int    g_batch[NUM_N];
__device__ int    g_deg[NUM_N];
__device__ float  g_dinv[NUM_N];
__device__ int    g_woff[NUM_N];
__device__ int    g_csrc[NUM_E];
__device__ int    g_bsum[GRID];
__device__ int    g_pcnt[NUM_G];
__device__ int    g_pcnt2[NUM_G];
__device__ int    g_boff[NUM_G];
__device__ int    g_boff2[NUM_G];
__device__ int    g_bnode[NUM_N];
__device__ __half g_h1h[NUM_N * 16];   // (x @ W1) * dinv, fp16
__device__ __half g_qh [NUM_N * 16];   // relu(layer1) * dinv, fp16
__device__ float  g_r  [NUM_N * 16];   // layer2 aggregate, fp32

// -------- software grid barrier -------------------------------------------
__device__ __forceinline__ void grid_sync(int j) {
    __syncthreads();
    __threadfence();
    if (threadIdx.x == 0) {
        if (atomicAdd(&g_bar[j], 1) == GRID - 1) {
            atomicExch(&g_bar[(j + 4) % 6], 0);
        } else {
            while (*((volatile int*)&g_bar[j]) < GRID) { }
        }
    }
    __syncthreads();
    __threadfence();
}

__device__ __forceinline__ void gather16h(const __half* base, int s, int sub,
                                          float& ax, float& ay, float& az, float& aw) {
    uint2 u = ((const uint2*)(base))[s * 4 + sub];
    float2 f0 = __half22float2(*(__half2*)&u.x);
    float2 f1 = __half22float2(*(__half2*)&u.y);
    ax += f0.x; ay += f0.y; az += f1.x; aw += f1.y;
}

__global__ __launch_bounds__(TPB, 1) void mega_kernel(
    const float* __restrict__ x, const void* ei, const void* bat,
    const float* __restrict__ W1, const float* __restrict__ b1,
    const float* __restrict__ W2, const float* __restrict__ b2,
    const float* __restrict__ LW1, const float* __restrict__ Lb1,
    const float* __restrict__ LW2, const float* __restrict__ Lb2,
    float* __restrict__ out)
{
    __shared__ float4 w1s[512];
    __shared__ float4 w2s[512];
    __shared__ float4 red[1024];
    __shared__ int    wsum[32];
    __shared__ int    s_i32, s_base;
    __shared__ float  ps[128], z1[128], z2[2];

    const int tid  = threadIdx.x, bid = blockIdx.x;
    const int lane = tid & 31,    wid = tid >> 5;
    const int gth  = bid * TPB + tid;
    const int gw   = gth >> 5;

    // ---- detect int64 vs int32 index layout ----
    if (tid == 0) s_i32 = 0;
    __syncthreads();
    if (tid < 64) {
        long long v = ((const long long*)ei)[(size_t)tid * (NUM_E / 64)];
        if (v < 0 || v >= (long long)NUM_N) s_i32 = 1;
    }
    __syncthreads();
    const bool f64 = (s_i32 == 0);

    // ================= P0: histograms (4 edges/thread/iter) ================
    for (int i = gth; i < NE2; i += 2 * GT) {
        int d0, d1;
        if (f64) { int4 v = ((const int4*)ei)[NE2 + i]; d0 = v.x; d1 = v.z; }
        else     { int2 v = ((const int2*)ei)[NE2 + i]; d0 = v.x; d1 = v.y; }
        int i2 = i + GT;
        int d2 = -1, d3 = -1;
        if (i2 < NE2) {
            if (f64) { int4 v = ((const int4*)ei)[NE2 + i2]; d2 = v.x; d3 = v.z; }
            else     { int2 v = ((const int2*)ei)[NE2 + i2]; d2 = v.x; d3 = v.y; }
        }
        atomicAdd(&g_deg[d0], 1);
        atomicAdd(&g_deg[d1], 1);
        if (i2 < NE2) { atomicAdd(&g_deg[d2], 1); atomicAdd(&g_deg[d3], 1); }
    }
    for (int i = gth; i < NUM_N; i += GT) {
        int b = f64 ? (int)((const long long*)bat)[i] : ((const int*)bat)[i];
        g_batch[i] = b;
        atomicAdd(&g_pcnt[b], 1);
    }
    grid_sync(0);

    // ================= P1: block-local scan of deg (+dinv, batch scan) =====
    const int node = bid * CHUNK + tid;
    const bool nvalid = (tid < CHUNK) && (node < NUM_N);
    int deg = nvalid ? g_deg[node] : 0;
    int v = deg;
    #pragma unroll
    for (int o = 1; o < 32; o <<= 1) {
        int n = __shfl_up_sync(~0u, v, o);
        if (lane >= o) v += n;
    }
    if (lane == 31) wsum[wid] = v;
    __syncthreads();
    if (wid == 0) {
        int wv = wsum[lane];
        #pragma unroll
        for (int o = 1; o < 32; o <<= 1) {
            int n = __shfl_up_sync(~0u, wv, o);
            if (lane >= o) wv += n;
        }
        wsum[lane] = wv;
    }
    __syncthreads();
    const int ex_local = (wid ? wsum[wid - 1] : 0) + v - deg;
    if (tid == 0) g_bsum[bid] = wsum[31];
    if (nvalid) g_dinv[node] = rsqrtf((float)deg + 1.f);
    if (bid == 0 && wid == 31) {
        int p0 = g_pcnt[lane*4+0], p1 = g_pcnt[lane*4+1];
        int p2 = g_pcnt[lane*4+2], p3 = g_pcnt[lane*4+3];
        int t1 = p0 + p1, t2 = t1 + p2, t3 = t2 + p3;
        int vv = t3;
        #pragma unroll
        for (int o = 1; o < 32; o <<= 1) {
            int n = __shfl_up_sync(~0u, vv, o);
            if (lane >= o) vv += n;
        }
        int exb = vv - t3;
        g_boff [lane*4+0] = exb;      g_boff2[lane*4+0] = exb;
        g_boff [lane*4+1] = exb+p0;   g_boff2[lane*4+1] = exb+p0;
        g_boff [lane*4+2] = exb+t1;   g_boff2[lane*4+2] = exb+t1;
        g_boff [lane*4+3] = exb+t2;   g_boff2[lane*4+3] = exb+t2;
        g_pcnt2[lane*4+0] = p0; g_pcnt2[lane*4+1] = p1;
        g_pcnt2[lane*4+2] = p2; g_pcnt2[lane*4+3] = p3;
    }
    grid_sync(1);

    // ================= P2: per-block global base, write woff ===============
    if (wid == 0) {
        int s = 0;
        for (int i = lane; i < bid; i += 32) s += g_bsum[i];
        #pragma unroll
        for (int o = 16; o; o >>= 1) s += __shfl_xor_sync(~0u, s, o);
        if (lane == 0) s_base = s;
    }
    __syncthreads();
    if (nvalid) g_woff[node] = s_base + ex_local;
    grid_sync(2);

    // ================= P3: scatter (4 edges/thread/iter) + bnode + gemm1 ===
    for (int i = gth; i < NE2; i += 2 * GT) {
        int s0, s1, d0, d1;
        if (f64) {
            int4 sv = ((const int4*)ei)[i];       s0 = sv.x; s1 = sv.z;
            int4 dv = ((const int4*)ei)[NE2 + i]; d0 = dv.x; d1 = dv.z;
        } else {
            int2 sv = ((const int2*)ei)[i];       s0 = sv.x; s1 = sv.y;
            int2 dv = ((const int2*)ei)[NE2 + i]; d0 = dv.x; d1 = dv.y;
        }
        int i2 = i + GT;
        int s2 = 0, s3 = 0, d2 = 0, d3 = 0;
        bool have2 = (i2 < NE2);
        if (have2) {
            if (f64) {
                int4 sv = ((const int4*)ei)[i2];       s2 = sv.x; s3 = sv.z;
                int4 dv = ((const int4*)ei)[NE2 + i2]; d2 = dv.x; d3 = dv.z;
            } else {
                int2 sv = ((const int2*)ei)[i2];       s2 = sv.x; s3 = sv.y;
                int2 dv = ((const int2*)ei)[NE2 + i2]; d2 = dv.x; d3 = dv.y;
            }
        }
        int p0 = atomicAdd(&g_woff[d0], 1);
        int p1 = atomicAdd(&g_woff[d1], 1);
        int p2 = 0, p3 = 0;
        if (have2) {
            p2 = atomicAdd(&g_woff[d2], 1);
            p3 = atomicAdd(&g_woff[d3], 1);
        }
        g_csrc[p0] = s0;
        g_csrc[p1] = s1;
        if (have2) { g_csrc[p2] = s2; g_csrc[p3] = s3; }
    }
    for (int i = gth; i < NUM_N; i += GT) {
        int b = g_batch[i];
        g_bnode[atomicAdd(&g_boff[b], 1)] = i;
    }
    for (int i = tid; i < 512; i += TPB) w1s[i] = ((const float4*)W1)[i];
    __syncthreads();
    {   // gemm1, double-buffered x row, fp16 output (dinv fused)
        int w = gw;
        float4 xv = make_float4(0.f, 0.f, 0.f, 0.f);
        if (w < NUM_N) xv = ((const float4*)x)[(size_t)w * 32 + lane];
        for (; w < NUM_N; w += NWARP) {
            int wn = w + NWARP;
            float4 xvN = make_float4(0.f, 0.f, 0.f, 0.f);
            if (wn < NUM_N) xvN = ((const float4*)x)[(size_t)wn * 32 + lane];
            float dvd = g_dinv[w];
            float a[16];
            #pragma unroll
            for (int j = 0; j < 16; j++) a[j] = 0.f;
            {
                float xs[4] = {xv.x, xv.y, xv.z, xv.w};
                int kb4 = lane * 16;
                #pragma unroll
                for (int kk = 0; kk < 4; kk++) {
                    float c = xs[kk];
                    #pragma unroll
                    for (int q = 0; q < 4; q++) {
                        float4 wv = w1s[kb4 + kk * 4 + q];
                        a[q*4+0] = fmaf(c, wv.x, a[q*4+0]);
                        a[q*4+1] = fmaf(c, wv.y, a[q*4+1]);
                        a[q*4+2] = fmaf(c, wv.z, a[q*4+2]);
                        a[q*4+3] = fmaf(c, wv.w, a[q*4+3]);
                    }
                }
            }
            {   // halving butterfly
                float t[16];
                #pragma unroll
                for (int i = 0; i < 16; i++) t[i] = __shfl_xor_sync(~0u, a[i], 16);
                if ((lane & 16) == 0) {
                    #pragma unroll
                    for (int i = 0; i < 8; i++) a[i] += t[i]; }
                else {
                    #pragma unroll
                    for (int i = 0; i < 8; i++) a[i] = a[i+8] + t[i+8]; }
            }
            {
                float t[8];
                #pragma unroll
                for (int i = 0; i < 8; i++) t[i] = __shfl_xor_sync(~0u, a[i], 8);
                if ((lane & 8) == 0) {
                    #pragma unroll
                    for (int i = 0; i < 4; i++) a[i] += t[i]; }
                else {
                    #pragma unroll
                    for (int i = 0; i < 4; i++) a[i] = a[i+4] + t[i+4]; }
            }
            {
                float t[4];
                #pragma unroll
                for (int i = 0; i < 4; i++) t[i] = __shfl_xor_sync(~0u, a[i], 4);
                if ((lane & 4) == 0) { a[0] += t[0]; a[1] += t[1]; }
                else                 { a[0] = a[2] + t[2]; a[1] = a[3] + t[3]; }
            }
            {
                float t0 = __shfl_xor_sync(~0u, a[0], 2);
                float t1 = __shfl_xor_sync(~0u, a[1], 2);
                if ((lane & 2) == 0) a[0] += t0; else a[0] = a[1] + t1;
            }
            a[0] += __shfl_xor_sync(~0u, a[0], 1);
            // even lanes hold dim = lane/2; pack pairs into half2 on lane%4==0
            float vres = a[0] * dvd;
            float vhi = __shfl_down_sync(~0u, vres, 2);
            if ((lane & 3) == 0)
                ((__half2*)g_h1h)[(size_t)w * 8 + (lane >> 2)] =
                    __floats2half2_rn(vres, vhi);
            xv = xvN;
        }
    }
    grid_sync(3);

    // ================= P4: prop1 (fp16 gathers, pipelined) =================
    if (bid == GRID - 1 && tid < NUM_G) g_pcnt[tid] = 0;
    {
        const int sub = lane & 3, grp = lane >> 2;
        int w = gw;
        int dgC = 0, stC = 0;
        if (w < NUM_N) { dgC = g_deg[w]; stC = g_woff[w] - dgC; }
        for (; w < NUM_N; w += NWARP) {
            int wn = w + NWARP;
            int dgN = 0, stN = 0;
            if (wn < NUM_N) { dgN = g_deg[wn]; stN = g_woff[wn] - dgN; }
            float ax0=0.f, ay0=0.f, az0=0.f, aw0=0.f;
            float ax1=0.f, ay1=0.f, az1=0.f, aw1=0.f;
            for (int e = grp; e < dgC; e += 16) {
                int e1 = e + 8;
                bool pr = (e1 < dgC);
                int s0 = g_csrc[stC + e];
                int s1 = pr ? g_csrc[stC + e1] : 0;
                gather16h(g_h1h, s0, sub, ax0, ay0, az0, aw0);
                if (pr) gather16h(g_h1h, s1, sub, ax1, ay1, az1, aw1);
            }
            float ax = ax0 + ax1, ay = ay0 + ay1, az = az0 + az1, aw = aw0 + aw1;
            #pragma unroll
            for (int o = 4; o < 32; o <<= 1) {
                ax += __shfl_xor_sync(~0u, ax, o);
                ay += __shfl_xor_sync(~0u, ay, o);
                az += __shfl_xor_sync(~0u, az, o);
                aw += __shfl_xor_sync(~0u, aw, o);
            }
            if (lane < 4) {
                float dvd = g_dinv[w];
                float hx=0.f, hy=0.f, hz=0.f, hw=0.f;
                gather16h(g_h1h, w, sub, hx, hy, hz, hw);
                float4 bv = ((const float4*)b1)[sub];
                float ox = fmaxf(fmaf(dvd, ax + hx, bv.x), 0.f) * dvd;
                float oy = fmaxf(fmaf(dvd, ay + hy, bv.y), 0.f) * dvd;
                float oz = fmaxf(fmaf(dvd, az + hz, bv.z), 0.f) * dvd;
                float ow = fmaxf(fmaf(dvd, aw + hw, bv.w), 0.f) * dvd;
                uint2 u;
                *(__half2*)&u.x = __floats2half2_rn(ox, oy);
                *(__half2*)&u.y = __floats2half2_rn(oz, ow);
                ((uint2*)g_qh)[(size_t)w * 4 + sub] = u;
            }
            dgC = dgN; stC = stN;
        }
    }
    grid_sync(4);

    // ================= P5: prop2 (fp16 gathers) ============================
    {
        const int sub = lane & 3, grp = lane >> 2;
        int w = gw;
        int dgC = 0, stC = 0;
        if (w < NUM_N) { dgC = g_deg[w]; stC = g_woff[w] - dgC; }
        for (; w < NUM_N; w += NWARP) {
            int wn = w + NWARP;
            int dgN = 0, stN = 0;
            if (wn < NUM_N) { dgN = g_deg[wn]; stN = g_woff[wn] - dgN; }
            float ax0=0.f, ay0=0.f, az0=0.f, aw0=0.f;
            float ax1=0.f, ay1=0.f, az1=0.f, aw1=0.f;
            for (int e = grp; e < dgC; e += 16) {
                int e1 = e + 8;
                bool pr = (e1 < dgC);
                int s0 = g_csrc[stC + e];
                int s1 = pr ? g_csrc[stC + e1] : 0;
                gather16h(g_qh, s0, sub, ax0, ay0, az0, aw0);
                if (pr) gather16h(g_qh, s1, sub, ax1, ay1, az1, aw1);
            }
            float ax = ax0 + ax1, ay = ay0 + ay1, az = az0 + az1, aw = aw0 + aw1;
            #pragma unroll
            for (int o = 4; o < 32; o <<= 1) {
                ax += __shfl_xor_sync(~0u, ax, o);
                ay += __shfl_xor_sync(~0u, ay, o);
                az += __shfl_xor_sync(~0u, az, o);
                aw += __shfl_xor_sync(~0u, aw, o);
            }
            if (lane < 4) {
                float dvd = g_dinv[w];
                float qx=0.f, qy=0.f, qz=0.f, qw=0.f;
                gather16h(g_qh, w, sub, qx, qy, qz, qw);
                float4 o;
                o.x = dvd * (ax + qx); o.y = dvd * (ay + qy);
                o.z = dvd * (az + qz); o.w = dvd * (aw + qw);
                ((float4*)g_r)[(size_t)w * 4 + sub] = o;
            }
            dgC = dgN; stC = stN;
        }
    }
    grid_sync(5);

    // ================= P6: pool + gemm2 + mlp (blocks 0..127) ==============
    if (bid < NUM_G) {
        for (int i = tid; i < 512; i += TPB) w2s[i] = ((const float4*)W2)[i];
        __syncthreads();
        const int g = bid;
        const int cnt = g_pcnt2[g];
        const int start = g_boff2[g];
        float4 bv = ((const float4*)b2)[lane];
        float4 sum = make_float4(0.f, 0.f, 0.f, 0.f);
        int i = wid;
        float rvN = 0.f;
        if (i < cnt) {
            int n = g_bnode[start + i];
            rvN = (lane < 16) ? g_r[n * 16 + lane] : 0.f;
        }
        for (; i < cnt; i += 32) {
            float rv = rvN;
            int in2 = i + 32;
            if (in2 < cnt) {
                int n2 = g_bnode[start + in2];
                rvN = (lane < 16) ? g_r[n2 * 16 + lane] : 0.f;
            }
            float4 acc = bv;
            #pragma unroll
            for (int k = 0; k < 16; k++) {
                float s = __shfl_sync(~0u, rv, k);
                float4 wv = w2s[k * 32 + lane];
                acc.x = fmaf(s, wv.x, acc.x); acc.y = fmaf(s, wv.y, acc.y);
                acc.z = fmaf(s, wv.z, acc.z); acc.w = fmaf(s, wv.w, acc.w);
            }
            sum.x += fmaxf(acc.x, 0.f); sum.y += fmaxf(acc.y, 0.f);
            sum.z += fmaxf(acc.z, 0.f); sum.w += fmaxf(acc.w, 0.f);
        }
        red[wid * 32 + lane] = sum;
        __syncthreads();
        if (tid < 32) {
            float4 tot = red[tid];
            #pragma unroll
            for (int w2 = 1; w2 < 32; w2++) {
                float4 vv = red[w2 * 32 + tid];
                tot.x += vv.x; tot.y += vv.y; tot.z += vv.z; tot.w += vv.w;
            }
            float inv = 1.f / fmaxf((float)cnt, 1.f);
            ps[tid * 4 + 0] = tot.x * inv; ps[tid * 4 + 1] = tot.y * inv;
            ps[tid * 4 + 2] = tot.z * inv; ps[tid * 4 + 3] = tot.w * inv;
        }
        __syncthreads();
        if (tid < 128) {
            float acc = Lb1[tid];
            #pragma unroll 8
            for (int k = 0; k < 128; k++) acc = fmaf(ps[k], LW1[k * 128 + tid], acc);
            z1[tid] = fmaxf(acc, 0.f);
        }
        __syncthreads();
        if (tid < 2) {
            float a = Lb2[tid];
            for (int k = 0; k < 128; k++) a = fmaf(z1[k], LW2[k * 2 + tid], a);
            z2[tid] = a;
        }
        __syncthreads();
        if (tid == 0) {
            float m = fmaxf(z2[0], z2[1]);
            float lse = m + logf(expf(z2[0] - m) + expf(z2[1] - m));
            out[g * 2 + 0] = z2[0] - lse;
            out[g * 2 + 1] = z2[1] - lse;
        }
    } else {
        for (int i = (bid - NUM_G) * TPB + tid; i < NUM_N; i += (GRID - NUM_G) * TPB)
            g_deg[i] = 0;
    }
}

// -------- launch --------
extern "C" void kernel_launch(void* const* d_in, const int* in_sizes, int n_in,
                              void* d_out, int out_size) {
    const float* x   = (const float*)d_in[0];
    const void*  ei  = d_in[1];
    const void*  bat = d_in[2];
    const float* W1  = (const float*)d_in[3];
    const float* b1  = (const float*)d_in[4];
    const float* W2  = (const float*)d_in[5];
    const float* b2  = (const float*)d_in[6];
    const float* LW1 = (const float*)d_in[7];
    const float* Lb1 = (const float*)d_in[8];
    const float* LW2 = (const float*)d_in[9];
    const float* Lb2 = (const float*)d_in[10];
    float* out = (float*)d_out;

    mega_kernel<<<GRID, TPB>>>(x, ei, bat, W1, b1, W2, b2,
                               LW1, Lb1, LW2, Lb2, out);
}